// round 1
// baseline (speedup 1.0000x reference)
#include <cuda_runtime.h>
#include <cstdint>
#include <cstddef>

// Problem constants
#define KVLEN   4096
#define QLEN    4
#define NEWPOS  4092          // KVLEN - QLEN : first "new token" position
#define NSPLIT  16
#define CHUNK   256           // KVLEN / NSPLIT

// Partial buffers: g_po[split][b*8+h][dl*16 + q]  (dl = dim 0..127, q = query 0..15)
static __device__ float g_po[(size_t)NSPLIT * 256 * 2048];
static __device__ float g_pl[NSPLIT * 256 * 16];

// ---- packed f32x2 helpers (Blackwell) ----
__device__ __forceinline__ float2 ffma2(float2 a, float2 b, float2 c) {
    float2 d;
    asm("fma.rn.f32x2 %0, %1, %2, %3;"
        : "=l"(*reinterpret_cast<unsigned long long*>(&d))
        : "l"(*reinterpret_cast<unsigned long long*>(&a)),
          "l"(*reinterpret_cast<unsigned long long*>(&b)),
          "l"(*reinterpret_cast<unsigned long long*>(&c)));
    return d;
}
__device__ __forceinline__ float2 fmul2(float2 a, float2 b) {
    float2 d;
    asm("mul.rn.f32x2 %0, %1, %2;"
        : "=l"(*reinterpret_cast<unsigned long long*>(&d))
        : "l"(*reinterpret_cast<unsigned long long*>(&a)),
          "l"(*reinterpret_cast<unsigned long long*>(&b)));
    return d;
}
__device__ __forceinline__ float2 fadd2(float2 a, float2 b) {
    float2 d;
    asm("add.rn.f32x2 %0, %1, %2;"
        : "=l"(*reinterpret_cast<unsigned long long*>(&d))
        : "l"(*reinterpret_cast<unsigned long long*>(&a)),
          "l"(*reinterpret_cast<unsigned long long*>(&b)));
    return d;
}
__device__ __forceinline__ float ex2f(float x) {
    float y;
    asm("ex2.approx.ftz.f32 %0, %1;" : "=f"(y) : "f"(x));
    return y;
}

// grid = (NSPLIT, H_KV=8, B=32), block = 256
__global__ void __launch_bounds__(256, 1) attn_main(
    const float* __restrict__ gq,    // (128, 4096)  query
    const float* __restrict__ gknew, // (128, 1024)  key (new)
    const float* __restrict__ gvnew, // (128, 1024)  value (new)
    const float* __restrict__ gkc,   // (8192,16,8,128) key cache
    const float* __restrict__ gvc,   // value cache
    const int*   __restrict__ gbt)   // (32, 256) block tables
{
    const int s    = blockIdx.x;   // split
    const int h    = blockIdx.y;   // kv head
    const int b    = blockIdx.z;   // batch
    const int tid  = threadIdx.x;
    const int warp = tid >> 5;
    const int lane = tid & 31;

    __shared__ __align__(16) float  qsm[2048];       // 16 queries x 128 dims (prescaled)
    __shared__ __align__(16) float  pbuf[8][2][16];  // per-warp double-buffered probs
    __shared__ float4 redo4[4][16][32];              // cross-warp o reduce (conflict-free)
    __shared__ float  redl[4][16];

    // ---------- stage Q into shared, prescaled by sm_scale * log2(e) ----------
    {
        const int qi    = tid >> 4;          // 0..15  (qi = qpos*4 + g)
        const int dbase = (tid & 15) * 8;    // 0..120
        const int qpos  = qi >> 2, g = qi & 3;
        const float SC  = 0.08838834764831845f * 1.4426950408889634f;
        const float* src = gq + (size_t)(b * 4 + qpos) * 4096 + (h * 4 + g) * 128 + dbase;
        float4 a = *(const float4*)src;
        float4 c = *(const float4*)(src + 4);
        a.x *= SC; a.y *= SC; a.z *= SC; a.w *= SC;
        c.x *= SC; c.y *= SC; c.z *= SC; c.w *= SC;
        *(float4*)(qsm + qi * 128 + dbase)     = a;
        *(float4*)(qsm + qi * 128 + dbase + 4) = c;
    }
    __syncthreads();

    // each lane keeps its 4-dim slice of all 16 queries, as packed float2 pairs
    float2 qpk[16][2];
#pragma unroll
    for (int i = 0; i < 16; i++) {
        float4 a = *(const float4*)(qsm + i * 128 + lane * 4);
        qpk[i][0] = make_float2(a.x, a.y);
        qpk[i][1] = make_float2(a.z, a.w);
    }

    const int S0  = s * CHUNK + warp * 32;          // first position for this warp
    const int bt0 = gbt[b * 256 + (S0 >> 4)];
    const int bt1 = gbt[b * 256 + (S0 >> 4) + 1];
    const float* kbase = gkc + h * 128 + lane * 4;
    const float* vbase = gvc + h * 128 + lane * 4;
    const float* knb   = gknew + (size_t)(b * 4) * 1024 + h * 128 + lane * 4;
    const float* vnb   = gvnew + (size_t)(b * 4) * 1024 + h * 128 + lane * 4;

    auto addr_of = [&](const float* cbase, const float* nbase, int tt) -> const float* {
        const int off = tt & 31;
        const int p   = S0 + off;
        if (p >= NEWPOS) return nbase + (p - NEWPOS) * 1024;
        const int blk = (off < 16) ? bt0 : bt1;
        return cbase + (size_t)blk * 16384 + (off & 15) * 1024;
    };

    // prefetch depth 2
    float4 kf[2], vf[2];
    kf[0] = *(const float4*)addr_of(kbase, knb, 0);
    vf[0] = *(const float4*)addr_of(vbase, vnb, 0);
    kf[1] = *(const float4*)addr_of(kbase, knb, 1);
    vf[1] = *(const float4*)addr_of(vbase, vnb, 1);

    float2 oacc[8][4];
#pragma unroll
    for (int j = 0; j < 8; j++)
#pragma unroll
        for (int d = 0; d < 4; d++) oacc[j][d] = make_float2(0.f, 0.f);
    float lsum = 0.f;
    const int myqpos = (lane >> 3) & 3;   // q(lane) = (lane>>1)&15 ; qpos = q>>2

#pragma unroll 2
    for (int t = 0; t < 32; t++) {
        const float4 kk = kf[t & 1];
        const float4 vv = vf[t & 1];
        if (t < 30) {
            kf[t & 1] = *(const float4*)addr_of(kbase, knb, t + 2);
            vf[t & 1] = *(const float4*)addr_of(vbase, vnb, t + 2);
        }

        // ---- QK: lane-partial dots for 16 queries (packed math) ----
        const float2 k01 = make_float2(kk.x, kk.y);
        const float2 k23 = make_float2(kk.z, kk.w);
        float r[16];
#pragma unroll
        for (int i = 0; i < 16; i++) {
            float2 acc = fmul2(qpk[i][0], k01);
            acc = ffma2(qpk[i][1], k23, acc);
            r[i] = acc.x + acc.y;
        }

        // ---- value-halving butterfly reduce: 32 lanes x 16 vals -> S[(lane>>1)&15] ----
#pragma unroll
        for (int i = 0; i < 8; i++) {
            float sv = (lane & 16) ? r[i] : r[i + 8];
            float rv = __shfl_xor_sync(0xffffffffu, sv, 16);
            r[i] = (((lane & 16) ? r[i + 8] : r[i])) + rv;
        }
#pragma unroll
        for (int i = 0; i < 4; i++) {
            float sv = (lane & 8) ? r[i] : r[i + 4];
            float rv = __shfl_xor_sync(0xffffffffu, sv, 8);
            r[i] = (((lane & 8) ? r[i + 4] : r[i])) + rv;
        }
#pragma unroll
        for (int i = 0; i < 2; i++) {
            float sv = (lane & 4) ? r[i] : r[i + 2];
            float rv = __shfl_xor_sync(0xffffffffu, sv, 4);
            r[i] = (((lane & 4) ? r[i + 2] : r[i])) + rv;
        }
        {
            float sv = (lane & 2) ? r[0] : r[1];
            float rv = __shfl_xor_sync(0xffffffffu, sv, 2);
            r[0] = (((lane & 2) ? r[1] : r[0])) + rv;
        }
        r[0] += __shfl_xor_sync(0xffffffffu, r[0], 1);

        // ---- fixed-constant softmax numerator (exact: C cancels in o/l) ----
        float pe = ex2f(r[0] - 20.0f);
        const int p = S0 + t;
        if (p >= NEWPOS && (p - NEWPOS) > myqpos) pe = 0.f;  // causal mask on new tokens
        lsum += pe;

        // stage probs to shared so PV reads pre-paired float2 operands
        if (!(lane & 1)) pbuf[warp][t & 1][lane >> 1] = pe;
        __syncwarp();
        const float4 pA = *(const float4*)&pbuf[warp][t & 1][0];
        const float4 pB = *(const float4*)&pbuf[warp][t & 1][4];
        const float4 pC = *(const float4*)&pbuf[warp][t & 1][8];
        const float4 pD = *(const float4*)&pbuf[warp][t & 1][12];
        float2 pp[8];
        pp[0] = make_float2(pA.x, pA.y); pp[1] = make_float2(pA.z, pA.w);
        pp[2] = make_float2(pB.x, pB.y); pp[3] = make_float2(pB.z, pB.w);
        pp[4] = make_float2(pC.x, pC.y); pp[5] = make_float2(pC.z, pC.w);
        pp[6] = make_float2(pD.x, pD.y); pp[7] = make_float2(pD.z, pD.w);

        const float2 vp[4] = { make_float2(vv.x, vv.x), make_float2(vv.y, vv.y),
                               make_float2(vv.z, vv.z), make_float2(vv.w, vv.w) };
        // oacc[j][d] = (o[q=2j], o[q=2j+1]) at dim lane*4+d
#pragma unroll
        for (int j = 0; j < 8; j++)
#pragma unroll
            for (int d = 0; d < 4; d++)
                oacc[j][d] = ffma2(pp[j], vp[d], oacc[j][d]);
    }

    // ---------- cross-warp tree reduce (8 -> 1 warps) ----------
    for (int half = 4; half >= 1; half >>= 1) {
        if (warp >= half && warp < 2 * half) {
            const int slot = warp - half;
#pragma unroll
            for (int j = 0; j < 8; j++) {
                redo4[slot][j * 2 + 0][lane] =
                    make_float4(oacc[j][0].x, oacc[j][0].y, oacc[j][1].x, oacc[j][1].y);
                redo4[slot][j * 2 + 1][lane] =
                    make_float4(oacc[j][2].x, oacc[j][2].y, oacc[j][3].x, oacc[j][3].y);
            }
            if (!(lane & 1)) redl[slot][lane >> 1] = lsum;
        }
        __syncthreads();
        if (warp < half) {
#pragma unroll
            for (int j = 0; j < 8; j++) {
                float4 x = redo4[warp][j * 2 + 0][lane];
                float4 y = redo4[warp][j * 2 + 1][lane];
                oacc[j][0] = fadd2(oacc[j][0], make_float2(x.x, x.y));
                oacc[j][1] = fadd2(oacc[j][1], make_float2(x.z, x.w));
                oacc[j][2] = fadd2(oacc[j][2], make_float2(y.x, y.y));
                oacc[j][3] = fadd2(oacc[j][3], make_float2(y.z, y.w));
            }
            if (!(lane & 1)) lsum += redl[warp][lane >> 1];
        }
        __syncthreads();
    }

    // ---------- write per-split partials ----------
    if (warp == 0) {
        const size_t base = ((size_t)(s * 256) + b * 8 + h) * 2048;
#pragma unroll
        for (int j = 0; j < 8; j++)
#pragma unroll
            for (int d = 0; d < 4; d++) {
                const int dl = lane * 4 + d;
                *(float2*)&g_po[base + dl * 16 + 2 * j] = oacc[j][d];
            }
        if (!(lane & 1)) g_pl[(s * 256 + b * 8 + h) * 16 + (lane >> 1)] = lsum;
    }
}

// grid = 2048, block = 256 : out[token][hq*128+d] = sum_s o_part / sum_s l_part
__global__ void __launch_bounds__(256) attn_combine(float* __restrict__ out)
{
    const int idx = blockIdx.x * 256 + threadIdx.x;     // 0 .. 524287
    const int qq  = idx & 15;
    const int dl  = (idx >> 4) & 127;
    const int bh  = idx >> 11;                          // b*8 + h
    float acc = 0.f, l = 0.f;
#pragma unroll
    for (int ss = 0; ss < NSPLIT; ss++) {
        acc += g_po[(size_t)ss * 524288 + (size_t)bh * 2048 + dl * 16 + qq];
        l   += g_pl[ss * 4096 + bh * 16 + qq];
    }
    const int b = bh >> 3, hh = bh & 7, qpos = qq >> 2, g = qq & 3;
    out[(size_t)(b * 4 + qpos) * 4096 + (hh * 4 + g) * 128 + dl] = acc / l;
}

extern "C" void kernel_launch(void* const* d_in, const int* in_sizes, int n_in,
                              void* d_out, int out_size)
{
    const float* q   = (const float*)d_in[0];
    const float* k   = (const float*)d_in[1];
    const float* v   = (const float*)d_in[2];
    const float* kc  = (const float*)d_in[3];
    const float* vc  = (const float*)d_in[4];
    const int*   bt  = (const int*)d_in[5];
    (void)in_sizes; (void)n_in; (void)out_size; // d_in[6] (new_cache_slots) derivable

    attn_main<<<dim3(NSPLIT, 8, 32), 256>>>(q, k, v, kc, vc, bt);
    attn_combine<<<2048, 256>>>((float*)d_out);
}

// round 2
// speedup vs baseline: 1.1786x; 1.1786x over previous
#include <cuda_runtime.h>
#include <cstdint>
#include <cstddef>

// Problem constants
#define KVLEN   4096
#define QLEN    4
#define NEWPOS  4092          // KVLEN - QLEN : first "new token" position
#define NSPLIT  16
#define CHUNK   256           // KVLEN / NSPLIT

// Partial buffers: g_po[split][b*8+h][dl*16 + q]  (dl = dim 0..127, q = query 0..15)
static __device__ float g_po[(size_t)NSPLIT * 256 * 2048];
static __device__ float g_pl[NSPLIT * 256 * 16];

// ---- packed f32x2 helpers (Blackwell) ----
__device__ __forceinline__ float2 ffma2(float2 a, float2 b, float2 c) {
    float2 d;
    asm("fma.rn.f32x2 %0, %1, %2, %3;"
        : "=l"(*reinterpret_cast<unsigned long long*>(&d))
        : "l"(*reinterpret_cast<unsigned long long*>(&a)),
          "l"(*reinterpret_cast<unsigned long long*>(&b)),
          "l"(*reinterpret_cast<unsigned long long*>(&c)));
    return d;
}
__device__ __forceinline__ float2 fmul2(float2 a, float2 b) {
    float2 d;
    asm("mul.rn.f32x2 %0, %1, %2;"
        : "=l"(*reinterpret_cast<unsigned long long*>(&d))
        : "l"(*reinterpret_cast<unsigned long long*>(&a)),
          "l"(*reinterpret_cast<unsigned long long*>(&b)));
    return d;
}
__device__ __forceinline__ float2 fadd2(float2 a, float2 b) {
    float2 d;
    asm("add.rn.f32x2 %0, %1, %2;"
        : "=l"(*reinterpret_cast<unsigned long long*>(&d))
        : "l"(*reinterpret_cast<unsigned long long*>(&a)),
          "l"(*reinterpret_cast<unsigned long long*>(&b)));
    return d;
}
__device__ __forceinline__ float ex2f(float x) {
    float y;
    asm("ex2.approx.ftz.f32 %0, %1;" : "=f"(y) : "f"(x));
    return y;
}

// grid = (NSPLIT, H_KV=8, B=32), block = 256
__global__ void __launch_bounds__(256, 1) attn_main(
    const float* __restrict__ gq,    // (128, 4096)  query
    const float* __restrict__ gknew, // (128, 1024)  key (new)
    const float* __restrict__ gvnew, // (128, 1024)  value (new)
    const float* __restrict__ gkc,   // (8192,16,8,128) key cache
    const float* __restrict__ gvc,   // value cache
    const int*   __restrict__ gbt)   // (32, 256) block tables
{
    const int s    = blockIdx.x;   // split
    const int h    = blockIdx.y;   // kv head
    const int b    = blockIdx.z;   // batch
    const int tid  = threadIdx.x;
    const int warp = tid >> 5;
    const int lane = tid & 31;

    __shared__ __align__(16) float  qsm[2048];          // 16 queries x 128 dims (prescaled)
    __shared__ __align__(16) float  pbuf[8][2][4][16];  // warp, group-parity, token-in-group, q
    __shared__ float4 redo4[4][16][32];                 // cross-warp o reduce
    __shared__ float  redl[4][16];

    // ---------- stage Q into shared, prescaled by sm_scale * log2(e) ----------
    {
        const int qi    = tid >> 4;          // 0..15  (qi = qpos*4 + g)
        const int dbase = (tid & 15) * 8;    // 0..120
        const int qpos  = qi >> 2, g = qi & 3;
        const float SC  = 0.08838834764831845f * 1.4426950408889634f;
        const float* src = gq + (size_t)(b * 4 + qpos) * 4096 + (h * 4 + g) * 128 + dbase;
        float4 a = *(const float4*)src;
        float4 c = *(const float4*)(src + 4);
        a.x *= SC; a.y *= SC; a.z *= SC; a.w *= SC;
        c.x *= SC; c.y *= SC; c.z *= SC; c.w *= SC;
        *(float4*)(qsm + qi * 128 + dbase)     = a;
        *(float4*)(qsm + qi * 128 + dbase + 4) = c;
    }
    __syncthreads();

    // each lane keeps its 4-dim slice of all 16 queries, as packed float2 pairs
    float2 qpk[16][2];
#pragma unroll
    for (int i = 0; i < 16; i++) {
        float4 a = *(const float4*)(qsm + i * 128 + lane * 4);
        qpk[i][0] = make_float2(a.x, a.y);
        qpk[i][1] = make_float2(a.z, a.w);
    }

    const int S0  = s * CHUNK + warp * 32;          // first position for this warp
    const int bt0 = gbt[b * 256 + (S0 >> 4)];
    const int bt1 = gbt[b * 256 + (S0 >> 4) + 1];
    const float* kb0 = gkc + (size_t)bt0 * 16384 + h * 128 + lane * 4;
    const float* kb1 = gkc + (size_t)bt1 * 16384 + h * 128 + lane * 4;
    const float* vb0 = gvc + (size_t)bt0 * 16384 + h * 128 + lane * 4;
    const float* vb1 = gvc + (size_t)bt1 * 16384 + h * 128 + lane * 4;
    const float* knb = gknew + (size_t)(b * 4) * 1024 + h * 128 + lane * 4;
    const float* vnb = gvnew + (size_t)(b * 4) * 1024 + h * 128 + lane * 4;
    const bool tail  = (S0 + 32 > NEWPOS);          // only split 15, warp 7

    // rolling prefetch, depth = 4 tokens
    float4 kf[4], vf[4];
#pragma unroll
    for (int i = 0; i < 4; i++) {
        kf[i] = *(const float4*)(kb0 + i * 1024);
        vf[i] = *(const float4*)(vb0 + i * 1024);
    }

    float2 oacc[8][4];
#pragma unroll
    for (int j = 0; j < 8; j++)
#pragma unroll
        for (int d = 0; d < 4; d++) oacc[j][d] = make_float2(0.f, 0.f);
    float lsum = 0.f;
    const int myqpos = (lane >> 3) & 3;   // q(lane) = (lane>>1)&15 ; qpos = q>>2

    for (int g = 0; g < 8; g++) {
        // ---------------- scores for 4 tokens (independent chains -> ILP) ---------
        float pe4[4];
#pragma unroll
        for (int i = 0; i < 4; i++) {
            const float4 kk = kf[i];
            const float2 k01 = make_float2(kk.x, kk.y);
            const float2 k23 = make_float2(kk.z, kk.w);
            float r[16];
#pragma unroll
            for (int q = 0; q < 16; q++) {
                float2 acc = fmul2(qpk[q][0], k01);
                acc = ffma2(qpk[q][1], k23, acc);
                r[q] = acc.x + acc.y;
            }
            // value-halving butterfly: 32 lanes x 16 vals -> S[(lane>>1)&15] in all lanes
#pragma unroll
            for (int i2 = 0; i2 < 8; i2++) {
                float sv = (lane & 16) ? r[i2] : r[i2 + 8];
                float rv = __shfl_xor_sync(0xffffffffu, sv, 16);
                r[i2] = (((lane & 16) ? r[i2 + 8] : r[i2])) + rv;
            }
#pragma unroll
            for (int i2 = 0; i2 < 4; i2++) {
                float sv = (lane & 8) ? r[i2] : r[i2 + 4];
                float rv = __shfl_xor_sync(0xffffffffu, sv, 8);
                r[i2] = (((lane & 8) ? r[i2 + 4] : r[i2])) + rv;
            }
#pragma unroll
            for (int i2 = 0; i2 < 2; i2++) {
                float sv = (lane & 4) ? r[i2] : r[i2 + 2];
                float rv = __shfl_xor_sync(0xffffffffu, sv, 4);
                r[i2] = (((lane & 4) ? r[i2 + 2] : r[i2])) + rv;
            }
            {
                float sv = (lane & 2) ? r[0] : r[1];
                float rv = __shfl_xor_sync(0xffffffffu, sv, 2);
                r[0] = (((lane & 2) ? r[1] : r[0])) + rv;
            }
            r[0] += __shfl_xor_sync(0xffffffffu, r[0], 1);
            pe4[i] = ex2f(r[0] - 20.0f);   // fixed-constant softmax (C cancels in o/l)
        }

        // causal mask: only the single tail warp, last group (positions 4092+i)
        if (tail && g == 7) {
#pragma unroll
            for (int i = 1; i < 4; i++)
                if (i > myqpos) pe4[i] = 0.f;
        }

#pragma unroll
        for (int i = 0; i < 4; i++) {
            lsum += pe4[i];
            if (!(lane & 1)) pbuf[warp][g & 1][i][lane >> 1] = pe4[i];
        }

        // ---------------- prefetch K for next group --------------------------------
        if (g < 7) {
            if (tail && g == 6) {
#pragma unroll
                for (int i = 0; i < 4; i++) kf[i] = *(const float4*)(knb + i * 1024);
            } else {
#pragma unroll
                for (int i = 0; i < 4; i++) {
                    const int t = g * 4 + 4 + i;
                    const float* base = (t & 16) ? kb1 : kb0;
                    kf[i] = *(const float4*)(base + (t & 15) * 1024);
                }
            }
        }

        __syncwarp();

        // ---------------- PV for 4 tokens ------------------------------------------
#pragma unroll
        for (int i = 0; i < 4; i++) {
            const float4 vv = vf[i];
            const float4 pA = *(const float4*)&pbuf[warp][g & 1][i][0];
            const float4 pB = *(const float4*)&pbuf[warp][g & 1][i][4];
            const float4 pC = *(const float4*)&pbuf[warp][g & 1][i][8];
            const float4 pD = *(const float4*)&pbuf[warp][g & 1][i][12];
            float2 pp[8];
            pp[0] = make_float2(pA.x, pA.y); pp[1] = make_float2(pA.z, pA.w);
            pp[2] = make_float2(pB.x, pB.y); pp[3] = make_float2(pB.z, pB.w);
            pp[4] = make_float2(pC.x, pC.y); pp[5] = make_float2(pC.z, pC.w);
            pp[6] = make_float2(pD.x, pD.y); pp[7] = make_float2(pD.z, pD.w);

            const float2 vp[4] = { make_float2(vv.x, vv.x), make_float2(vv.y, vv.y),
                                   make_float2(vv.z, vv.z), make_float2(vv.w, vv.w) };
#pragma unroll
            for (int j = 0; j < 8; j++)
#pragma unroll
                for (int d = 0; d < 4; d++)
                    oacc[j][d] = ffma2(pp[j], vp[d], oacc[j][d]);
        }

        // ---------------- prefetch V for next group --------------------------------
        if (g < 7) {
            if (tail && g == 6) {
#pragma unroll
                for (int i = 0; i < 4; i++) vf[i] = *(const float4*)(vnb + i * 1024);
            } else {
#pragma unroll
                for (int i = 0; i < 4; i++) {
                    const int t = g * 4 + 4 + i;
                    const float* base = (t & 16) ? vb1 : vb0;
                    vf[i] = *(const float4*)(base + (t & 15) * 1024);
                }
            }
        }
    }

    // ---------- cross-warp tree reduce (8 -> 1 warps) ----------
    for (int half = 4; half >= 1; half >>= 1) {
        if (warp >= half && warp < 2 * half) {
            const int slot = warp - half;
#pragma unroll
            for (int j = 0; j < 8; j++) {
                redo4[slot][j * 2 + 0][lane] =
                    make_float4(oacc[j][0].x, oacc[j][0].y, oacc[j][1].x, oacc[j][1].y);
                redo4[slot][j * 2 + 1][lane] =
                    make_float4(oacc[j][2].x, oacc[j][2].y, oacc[j][3].x, oacc[j][3].y);
            }
            if (!(lane & 1)) redl[slot][lane >> 1] = lsum;
        }
        __syncthreads();
        if (warp < half) {
#pragma unroll
            for (int j = 0; j < 8; j++) {
                float4 x = redo4[warp][j * 2 + 0][lane];
                float4 y = redo4[warp][j * 2 + 1][lane];
                oacc[j][0] = fadd2(oacc[j][0], make_float2(x.x, x.y));
                oacc[j][1] = fadd2(oacc[j][1], make_float2(x.z, x.w));
                oacc[j][2] = fadd2(oacc[j][2], make_float2(y.x, y.y));
                oacc[j][3] = fadd2(oacc[j][3], make_float2(y.z, y.w));
            }
            if (!(lane & 1)) lsum += redl[warp][lane >> 1];
        }
        __syncthreads();
    }

    // ---------- write per-split partials ----------
    if (warp == 0) {
        const size_t base = ((size_t)(s * 256) + b * 8 + h) * 2048;
#pragma unroll
        for (int j = 0; j < 8; j++)
#pragma unroll
            for (int d = 0; d < 4; d++) {
                const int dl = lane * 4 + d;
                *(float2*)&g_po[base + dl * 16 + 2 * j] = oacc[j][d];
            }
        if (!(lane & 1)) g_pl[(s * 256 + b * 8 + h) * 16 + (lane >> 1)] = lsum;
    }
}

// grid = 2048, block = 256 : out[token][hq*128+d] = sum_s o_part / sum_s l_part
__global__ void __launch_bounds__(256) attn_combine(float* __restrict__ out)
{
    const int idx = blockIdx.x * 256 + threadIdx.x;     // 0 .. 524287
    const int qq  = idx & 15;
    const int dl  = (idx >> 4) & 127;
    const int bh  = idx >> 11;                          // b*8 + h
    float acc = 0.f, l = 0.f;
#pragma unroll
    for (int ss = 0; ss < NSPLIT; ss++) {
        acc += g_po[(size_t)ss * 524288 + (size_t)bh * 2048 + dl * 16 + qq];
        l   += g_pl[ss * 4096 + bh * 16 + qq];
    }
    const int b = bh >> 3, hh = bh & 7, qpos = qq >> 2, g = qq & 3;
    out[(size_t)(b * 4 + qpos) * 4096 + (hh * 4 + g) * 128 + dl] = acc / l;
}

extern "C" void kernel_launch(void* const* d_in, const int* in_sizes, int n_in,
                              void* d_out, int out_size)
{
    const float* q   = (const float*)d_in[0];
    const float* k   = (const float*)d_in[1];
    const float* v   = (const float*)d_in[2];
    const float* kc  = (const float*)d_in[3];
    const float* vc  = (const float*)d_in[4];
    const int*   bt  = (const int*)d_in[5];
    (void)in_sizes; (void)n_in; (void)out_size;

    attn_main<<<dim3(NSPLIT, 8, 32), 256>>>(q, k, v, kc, vc, bt);
    attn_combine<<<2048, 256>>>((float*)d_out);
}

// round 3
// speedup vs baseline: 1.9058x; 1.6170x over previous
#include <cuda_runtime.h>
#include <cstdint>
#include <cstddef>

// Problem constants
#define KVLEN   4096
#define QLEN    4
#define NEWPOS  4092
#define NSPLIT  8
#define CHUNKT  512            // tokens per CTA (KVLEN / NSPLIT)

// Partial buffers: g_po[split][b*8+h][dl*16 + q]
static __device__ float g_po[(size_t)NSPLIT * 256 * 2048];
static __device__ float g_pl[NSPLIT * 256 * 16];

// ---------------- shared memory layout (bytes) ----------------
#define KW_BYTES  (2 * 16 * 140 * 4)          // per-warp K: 2 bufs x 16 rows x 140 floats = 17920
#define OFF_K     0
#define OFF_V     (8 * KW_BYTES)              // 143360
#define VW_BYTES  (16 * 128 * 4)              // 8192
#define OFF_Q     (OFF_V + 8 * VW_BYTES)      // 208896
#define OFF_P     (OFF_Q + 16 * 136 * 4)      // 217600
#define PW_BYTES  (16 * 20 * 4)               // 1280
#define OFF_RL    (OFF_P + 8 * PW_BYTES)      // 227840
#define SMEM_TOTAL (OFF_RL + 256)             // 228096

// ---- packed f32x2 helpers (Blackwell) ----
__device__ __forceinline__ float2 ffma2(float2 a, float2 b, float2 c) {
    float2 d;
    asm("fma.rn.f32x2 %0, %1, %2, %3;"
        : "=l"(*reinterpret_cast<unsigned long long*>(&d))
        : "l"(*reinterpret_cast<unsigned long long*>(&a)),
          "l"(*reinterpret_cast<unsigned long long*>(&b)),
          "l"(*reinterpret_cast<unsigned long long*>(&c)));
    return d;
}
__device__ __forceinline__ float2 fadd2(float2 a, float2 b) {
    float2 d;
    asm("add.rn.f32x2 %0, %1, %2;"
        : "=l"(*reinterpret_cast<unsigned long long*>(&d))
        : "l"(*reinterpret_cast<unsigned long long*>(&a)),
          "l"(*reinterpret_cast<unsigned long long*>(&b)));
    return d;
}
__device__ __forceinline__ float ex2f(float x) {
    float y;
    asm("ex2.approx.ftz.f32 %0, %1;" : "=f"(y) : "f"(x));
    return y;
}
__device__ __forceinline__ void cp_async16(uint32_t dst, const void* src) {
    asm volatile("cp.async.cg.shared.global [%0], [%1], 16;"
                 :: "r"(dst), "l"(__cvta_generic_to_global(src)) : "memory");
}
__device__ __forceinline__ void cp_commit() {
    asm volatile("cp.async.commit_group;" ::: "memory");
}
__device__ __forceinline__ void cp_wait1() {
    asm volatile("cp.async.wait_group 1;" ::: "memory");
}

// grid = (NSPLIT, 8, 32), block = 256
__global__ void __launch_bounds__(256, 1) attn_main(
    const float* __restrict__ gq,    // (128, 4096)
    const float* __restrict__ gknew, // (128, 1024)
    const float* __restrict__ gvnew, // (128, 1024)
    const float* __restrict__ gkc,   // (8192,16,8,128)
    const float* __restrict__ gvc,
    const int*   __restrict__ gbt)   // (32, 256)
{
    extern __shared__ char sm_raw[];
    const int s    = blockIdx.x;
    const int h    = blockIdx.y;
    const int b    = blockIdx.z;
    const int tid  = threadIdx.x;
    const int warp = tid >> 5;
    const int lane = tid & 31;
    const int tok  = lane & 15;      // token within sub-tile
    const int hf   = lane >> 4;      // dim-half (0: d0-63, 1: d64-127)

    float* smQ = (float*)(sm_raw + OFF_Q);                    // [q][136], halves at +0 / +68
    float* smK = (float*)(sm_raw + OFF_K + warp * KW_BYTES);  // [buf][16 rows][140]
    float* smV = (float*)(sm_raw + OFF_V + warp * VW_BYTES);  // [16 rows][128]
    float* smP = (float*)(sm_raw + OFF_P + warp * PW_BYTES);  // [16 rows][20]
    const uint32_t aK = (uint32_t)__cvta_generic_to_shared(smK);
    const uint32_t aV = (uint32_t)__cvta_generic_to_shared(smV);

    const int S0     = s * CHUNKT + warp * 64;   // warp's first token
    const bool tailw = (S0 + 64 == KVLEN);       // s==7 && warp==7
    const int btidx  = b * 256 + (S0 >> 4);      // first block-table index (4 entries used)

    // -------- K tile issue: sub-tile stp (16 tokens = one cache block) into buf --------
    auto issue_k = [&](int stp, int buf, int blk) {
        const char* gsrc = (const char*)gkc + (size_t)blk * 65536 + (size_t)h * 512 + lane * 16;
        const uint32_t dst0 = aK + buf * 8960 + hf * 272 + ((lane * 16) & 255);
#pragma unroll
        for (int r = 0; r < 16; r++) {
            const char* src = gsrc + r * 4096;
            if (tailw && stp == 3 && r >= 12)
                src = (const char*)gknew + (size_t)(b * 4 + (r - 12)) * 4096 + (size_t)h * 512 + lane * 16;
            cp_async16(dst0 + r * 560, src);
        }
    };
    auto issue_v = [&](int stp, int blk) {
        const char* gsrc = (const char*)gvc + (size_t)blk * 65536 + (size_t)h * 512 + lane * 16;
        const uint32_t dst0 = aV + lane * 16;
#pragma unroll
        for (int r = 0; r < 16; r++) {
            const char* src = gsrc + r * 4096;
            if (tailw && stp == 3 && r >= 12)
                src = (const char*)gvnew + (size_t)(b * 4 + (r - 12)) * 4096 + (size_t)h * 512 + lane * 16;
            cp_async16(dst0 + r * 512, src);
        }
    };

    // -------- prologue: start K0, stage Q --------
    int blk_cur = gbt[btidx];
    issue_k(0, 0, blk_cur);
    cp_commit();                                   // pending: [K0]

    {   // Q staging, prescaled by sm_scale * log2(e), half-padded layout
        const int qi = tid >> 4;                  // 0..15
        const int d0 = (tid & 15) * 8;            // 0..120 (always within one 64-half)
        const int qpos = qi >> 2, g = qi & 3;
        const float SC = 0.08838834764831845f * 1.4426950408889634f;
        const float* src = gq + (size_t)(b * 4 + qpos) * 4096 + (h * 4 + g) * 128 + d0;
        float4 a = *(const float4*)src;
        float4 c = *(const float4*)(src + 4);
        a.x *= SC; a.y *= SC; a.z *= SC; a.w *= SC;
        c.x *= SC; c.y *= SC; c.z *= SC; c.w *= SC;
        const int w = qi * 136 + ((d0 & 64) ? (68 + (d0 - 64)) : d0);
        *(float4*)(smQ + w)     = a;
        *(float4*)(smQ + w + 4) = c;
    }
    __syncthreads();

    float2 oacc[8][4];
#pragma unroll
    for (int j = 0; j < 8; j++)
#pragma unroll
        for (int d = 0; d < 4; d++) oacc[j][d] = make_float2(0.f, 0.f);
    float2 l2[8];
#pragma unroll
    for (int j = 0; j < 8; j++) l2[j] = make_float2(0.f, 0.f);

#pragma unroll 1
    for (int st = 0; st < 4; st++) {
        const int buf = st & 1;
        // next block id (latency hidden under QK below)
        int blk_next = 0;
        if (st < 3) blk_next = gbt[btidx + st + 1];

        issue_v(st, blk_cur);
        cp_commit();            // pending: [K_st, V_st]
        cp_wait1();             // K_st done; V_st may still fly
        __syncwarp();

        // ---------------- QK: acc over this lane's 64 dims for 16 queries ----------
        float2 acc2[16];
#pragma unroll
        for (int q = 0; q < 16; q++) acc2[q] = make_float2(0.f, 0.f);
        const float* kb = smK + buf * 2240 + tok * 140 + hf * 68;
        const float* qb = smQ + hf * 68;
#pragma unroll
        for (int c = 0; c < 16; c++) {
            const float4 kk = *(const float4*)(kb + c * 4);
            const float2 k01 = make_float2(kk.x, kk.y);
            const float2 k23 = make_float2(kk.z, kk.w);
#pragma unroll
            for (int q = 0; q < 16; q++) {
                const float4 qv = *(const float4*)(qb + q * 136 + c * 4);
                float2 a01 = make_float2(qv.x, qv.y);
                float2 a23 = make_float2(qv.z, qv.w);
                acc2[q] = ffma2(a01, k01, acc2[q]);
                acc2[q] = ffma2(a23, k23, acc2[q]);
            }
        }

        // prefetch next K tile now (waited only next iteration)
        if (st < 3) issue_k(st + 1, buf ^ 1, blk_next);
        cp_commit();            // pending: [V_st, K_{st+1}]

        // ---------------- epilogue: one shfl level + exp ---------------------------
        float pe[16];
#pragma unroll
        for (int q = 0; q < 16; q++) {
            float sh = acc2[q].x + acc2[q].y;
            sh += __shfl_xor_sync(0xffffffffu, sh, 16);
            pe[q] = ex2f(sh - 20.0f);   // fixed-constant softmax (cancels in o/l)
        }
        // causal mask: only tail warp, last sub-tile, new-token rows 12..15
        if (tailw && st == 3 && tok >= 12) {
            const int nt = tok - 12;
#pragma unroll
            for (int q = 0; q < 16; q++)
                if (nt > (q >> 2)) pe[q] = 0.f;
        }
        if (hf == 0) {
            float* pr = smP + tok * 20;
            *(float4*)(pr)      = make_float4(pe[0],  pe[1],  pe[2],  pe[3]);
            *(float4*)(pr + 4)  = make_float4(pe[4],  pe[5],  pe[6],  pe[7]);
            *(float4*)(pr + 8)  = make_float4(pe[8],  pe[9],  pe[10], pe[11]);
            *(float4*)(pr + 12) = make_float4(pe[12], pe[13], pe[14], pe[15]);
        }

        cp_wait1();             // V_st done; K_{st+1} still flying
        __syncwarp();           // P + V visible warp-wide

        // ---------------- PV: dim-per-lane over 16 tokens ---------------------------
#pragma unroll
        for (int i = 0; i < 16; i++) {
            const float* pr = smP + i * 20;
            const float4 pA = *(const float4*)(pr);
            const float4 pB = *(const float4*)(pr + 4);
            const float4 pC = *(const float4*)(pr + 8);
            const float4 pD = *(const float4*)(pr + 12);
            const float4 vv = *(const float4*)(smV + i * 128 + lane * 4);
            float2 pp[8];
            pp[0] = make_float2(pA.x, pA.y); pp[1] = make_float2(pA.z, pA.w);
            pp[2] = make_float2(pB.x, pB.y); pp[3] = make_float2(pB.z, pB.w);
            pp[4] = make_float2(pC.x, pC.y); pp[5] = make_float2(pC.z, pC.w);
            pp[6] = make_float2(pD.x, pD.y); pp[7] = make_float2(pD.z, pD.w);
            const float2 vp0 = make_float2(vv.x, vv.x);
            const float2 vp1 = make_float2(vv.y, vv.y);
            const float2 vp2 = make_float2(vv.z, vv.z);
            const float2 vp3 = make_float2(vv.w, vv.w);
#pragma unroll
            for (int j = 0; j < 8; j++) {
                l2[j] = fadd2(l2[j], pp[j]);
                oacc[j][0] = ffma2(pp[j], vp0, oacc[j][0]);
                oacc[j][1] = ffma2(pp[j], vp1, oacc[j][1]);
                oacc[j][2] = ffma2(pp[j], vp2, oacc[j][2]);
                oacc[j][3] = ffma2(pp[j], vp3, oacc[j][3]);
            }
        }
        __syncwarp();           // PV reads done before next sub-tile's P store
        blk_cur = blk_next;
    }

    // ---------- cross-warp tree reduce (overlay on dead K-tile smem) ----------
    __syncthreads();
    float4* redo4 = (float4*)(sm_raw + OFF_K);   // [4][16][32] float4 = 32 KB
    float*  redl  = (float*)(sm_raw + OFF_RL);   // [4][16]
    // l2 is identical across lanes of a warp (accumulated from broadcast pp)
    for (int half = 4; half >= 1; half >>= 1) {
        if (warp >= half && warp < 2 * half) {
            const int slot = warp - half;
#pragma unroll
            for (int j = 0; j < 8; j++) {
                redo4[(slot * 16 + j * 2 + 0) * 32 + lane] =
                    make_float4(oacc[j][0].x, oacc[j][0].y, oacc[j][1].x, oacc[j][1].y);
                redo4[(slot * 16 + j * 2 + 1) * 32 + lane] =
                    make_float4(oacc[j][2].x, oacc[j][2].y, oacc[j][3].x, oacc[j][3].y);
            }
            if (lane < 8) *(float2*)&redl[slot * 16 + 2 * lane] = l2[lane];
        }
        __syncthreads();
        if (warp < half) {
#pragma unroll
            for (int j = 0; j < 8; j++) {
                float4 x = redo4[(warp * 16 + j * 2 + 0) * 32 + lane];
                float4 y = redo4[(warp * 16 + j * 2 + 1) * 32 + lane];
                oacc[j][0] = fadd2(oacc[j][0], make_float2(x.x, x.y));
                oacc[j][1] = fadd2(oacc[j][1], make_float2(x.z, x.w));
                oacc[j][2] = fadd2(oacc[j][2], make_float2(y.x, y.y));
                oacc[j][3] = fadd2(oacc[j][3], make_float2(y.z, y.w));
            }
            if (lane < 8) l2[lane] = fadd2(l2[lane], *(float2*)&redl[warp * 16 + 2 * lane]);
        }
        __syncthreads();
    }

    // ---------- write per-split partials ----------
    if (warp == 0) {
        const size_t base = ((size_t)(s * 256) + b * 8 + h) * 2048;
#pragma unroll
        for (int j = 0; j < 8; j++)
#pragma unroll
            for (int d = 0; d < 4; d++) {
                const int dl = lane * 4 + d;
                *(float2*)&g_po[base + dl * 16 + 2 * j] = oacc[j][d];
            }
        if (lane < 8)
            *(float2*)&g_pl[(s * 256 + b * 8 + h) * 16 + 2 * lane] = l2[lane];
    }
}

// grid = 2048, block = 256
__global__ void __launch_bounds__(256) attn_combine(float* __restrict__ out)
{
    const int idx = blockIdx.x * 256 + threadIdx.x;
    const int qq  = idx & 15;
    const int dl  = (idx >> 4) & 127;
    const int bh  = idx >> 11;
    float acc = 0.f, l = 0.f;
#pragma unroll
    for (int ss = 0; ss < NSPLIT; ss++) {
        acc += g_po[(size_t)ss * 524288 + (size_t)bh * 2048 + dl * 16 + qq];
        l   += g_pl[ss * 4096 + bh * 16 + qq];
    }
    const int b = bh >> 3, hh = bh & 7, qpos = qq >> 2, g = qq & 3;
    out[(size_t)(b * 4 + qpos) * 4096 + (hh * 4 + g) * 128 + dl] = acc / l;
}

extern "C" void kernel_launch(void* const* d_in, const int* in_sizes, int n_in,
                              void* d_out, int out_size)
{
    const float* q   = (const float*)d_in[0];
    const float* k   = (const float*)d_in[1];
    const float* v   = (const float*)d_in[2];
    const float* kc  = (const float*)d_in[3];
    const float* vc  = (const float*)d_in[4];
    const int*   bt  = (const int*)d_in[5];
    (void)in_sizes; (void)n_in; (void)out_size;

    cudaFuncSetAttribute(attn_main, cudaFuncAttributeMaxDynamicSharedMemorySize, SMEM_TOTAL);
    attn_main<<<dim3(NSPLIT, 8, 32), 256, SMEM_TOTAL>>>(q, k, v, kc, vc, bt);
    attn_combine<<<2048, 256>>>((float*)d_out);
}